// round 4
// baseline (speedup 1.0000x reference)
#include <cuda_runtime.h>
#include <float.h>

#define L_SEQ 4096
#define N_TOTAL 512
#define WPB 8   // warps (= kernels) per block

__device__ int g_inv[N_TOTAL];
__device__ int g_P;

// Build inverse permutation and recover P from group-0 metadata.
__global__ void setup_kernel(const int* __restrict__ perm,
                             const int* __restrict__ off0,
                             const int* __restrict__ lout0,
                             int n_perm) {
    int j = threadIdx.x;
    if (j < n_perm) g_inv[perm[j]] = j;
    if (j == 0) {
        // ks=7 group: off0[6]-off0[0] = 6*d ; lout = L + 2*pad - 6*d
        int d6  = off0[6] - off0[0];
        int pad = (lout0[0] - L_SEQ + d6) / 2;
        g_P = off0[0] + pad;
    }
}

template<int KS>
__device__ __forceinline__ void run_group(
    const float* __restrict__ sx,          // unpadded x[b], length L_SEQ
    const float* __restrict__ w, const float* __restrict__ bias,
    const int*  __restrict__ off, const int* __restrict__ lout,
    float* __restrict__ out, int gi, int base, int b, int stride)
{
    const int lane = threadIdx.x & 31;
    const int P = g_P;

    float wk[KS];
    int   ck[KS];                            // x index = ck[k] + t
#pragma unroll
    for (int k = 0; k < KS; k++) {
        wk[k] = __ldg(&w[gi * KS + k]);
        ck[k] = __ldg(&off[gi * KS + k]) - P;
    }
    const float bsv = __ldg(&bias[gi]);
    const int   lo  = __ldg(&lout[gi]);

    // ck is strictly increasing in k (off_k = P - pad + k*d, d >= 1).
    // Interior: all taps in [0, L) iff tl <= t < th.
    int tl = -ck[0];          if (tl < 0) tl = 0;   if (tl > lo) tl = lo;
    int th = L_SEQ - ck[KS-1];                      if (th > lo) th = lo;
    if (th < tl) th = tl;

    float mx  = -FLT_MAX;
    int   cnt = 0;
    int t = lane;

    // Phase A: leading boundary (checked taps, OOB reads as zero)
    for (; t < tl; t += 32) {
        float s = bsv;
#pragma unroll
        for (int k = 0; k < KS; k++) {
            int j = ck[k] + t;
            float v = ((unsigned)j < (unsigned)L_SEQ) ? sx[j] : 0.0f;
            s = fmaf(wk[k], v, s);
        }
        mx = fmaxf(mx, s);
        cnt += (s > 0.0f);
    }

    // Phase B: interior, unchecked, unroll-by-2
    for (; t + 32 < th; t += 64) {
        float s0 = bsv, s1 = bsv;
#pragma unroll
        for (int k = 0; k < KS; k++) {
            s0 = fmaf(wk[k], sx[ck[k] + t],      s0);
            s1 = fmaf(wk[k], sx[ck[k] + t + 32], s1);
        }
        mx = fmaxf(mx, fmaxf(s0, s1));
        cnt += (s0 > 0.0f);
        cnt += (s1 > 0.0f);
    }
    for (; t < th; t += 32) {
        float s = bsv;
#pragma unroll
        for (int k = 0; k < KS; k++)
            s = fmaf(wk[k], sx[ck[k] + t], s);
        mx = fmaxf(mx, s);
        cnt += (s > 0.0f);
    }

    // Phase C: trailing boundary (checked)
    for (; t < lo; t += 32) {
        float s = bsv;
#pragma unroll
        for (int k = 0; k < KS; k++) {
            int j = ck[k] + t;
            float v = ((unsigned)j < (unsigned)L_SEQ) ? sx[j] : 0.0f;
            s = fmaf(wk[k], v, s);
        }
        mx = fmaxf(mx, s);
        cnt += (s > 0.0f);
    }

    // warp reductions
#pragma unroll
    for (int o = 16; o; o >>= 1) {
        mx   = fmaxf(mx, __shfl_xor_sync(0xffffffffu, mx, o));
        cnt += __shfl_xor_sync(0xffffffffu, cnt, o);
    }

    if (lane == 0) {
        int col = g_inv[base + gi];
        out[b * stride + 2 * col]     = mx;
        out[b * stride + 2 * col + 1] = (float)cnt / (float)lo;
    }
}

__global__ __launch_bounds__(WPB * 32, 6)
void rocket_all_kernel(
    const float* __restrict__ x,
    const float* __restrict__ w0, const float* __restrict__ b0,
    const int*  __restrict__ off0, const int* __restrict__ lout0, int n0,
    const float* __restrict__ w1, const float* __restrict__ b1,
    const int*  __restrict__ off1, const int* __restrict__ lout1, int n1,
    const float* __restrict__ w2, const float* __restrict__ b2,
    const int*  __restrict__ off2, const int* __restrict__ lout2, int n2,
    float* __restrict__ out, int nb0, int nb1, int stride)
{
    __shared__ float sx[L_SEQ];
    const int b = blockIdx.y;

    // stage x[b] into shared, vectorized float4
    {
        const float4* xb4 = (const float4*)(x + (size_t)b * L_SEQ);
        float4* dst = (float4*)sx;
        for (int i = threadIdx.x; i < L_SEQ / 4; i += WPB * 32)
            dst[i] = xb4[i];
    }
    __syncthreads();

    const int warp = threadIdx.x >> 5;
    const int bx = blockIdx.x;

    if (bx < nb0) {
        int gi = bx * WPB + warp;
        if (gi < n0) run_group<7>(sx, w0, b0, off0, lout0, out, gi, 0, b, stride);
    } else if (bx < nb0 + nb1) {
        int gi = (bx - nb0) * WPB + warp;
        if (gi < n1) run_group<9>(sx, w1, b1, off1, lout1, out, gi, n0, b, stride);
    } else {
        int gi = (bx - nb0 - nb1) * WPB + warp;
        if (gi < n2) run_group<11>(sx, w2, b2, off2, lout2, out, gi, n0 + n1, b, stride);
    }
}

extern "C" void kernel_launch(void* const* d_in, const int* in_sizes, int n_in,
                              void* d_out, int out_size) {
    // Two possible input orderings; disambiguate via sizes.
    // Dict order:      x, perm, P, w0,b0,off0,lout0, w1,b1,off1,lout1, w2,b2,off2,lout2
    // Signature order: x, w0,b0,off0,lout0, w1,b1,off1,lout1, w2,b2,off2,lout2, perm, P
    int ix, iperm, ig0, ig1, ig2;
    if (n_in >= 3 && in_sizes[1] == N_TOTAL && in_sizes[2] == 1) {
        ix = 0; iperm = 1; ig0 = 3; ig1 = 7; ig2 = 11;          // dict order
    } else {
        ix = 0; ig0 = 1; ig1 = 5; ig2 = 9; iperm = 13;          // signature order
    }

    const float* x     = (const float*)d_in[ix];
    const int*   perm  = (const int*)  d_in[iperm];

    const float* w0    = (const float*)d_in[ig0 + 0];
    const float* b0    = (const float*)d_in[ig0 + 1];
    const int*   off0  = (const int*)  d_in[ig0 + 2];
    const int*   lout0 = (const int*)  d_in[ig0 + 3];
    const float* w1    = (const float*)d_in[ig1 + 0];
    const float* b1    = (const float*)d_in[ig1 + 1];
    const int*   off1  = (const int*)  d_in[ig1 + 2];
    const int*   lout1 = (const int*)  d_in[ig1 + 3];
    const float* w2    = (const float*)d_in[ig2 + 0];
    const float* b2    = (const float*)d_in[ig2 + 1];
    const int*   off2  = (const int*)  d_in[ig2 + 2];
    const int*   lout2 = (const int*)  d_in[ig2 + 3];

    const int n0 = in_sizes[ig0 + 1];
    const int n1 = in_sizes[ig1 + 1];
    const int n2 = in_sizes[ig2 + 1];
    const int B  = in_sizes[ix] / L_SEQ;
    const int N  = n0 + n1 + n2;
    const int stride = 2 * N;

    setup_kernel<<<1, N_TOTAL>>>(perm, off0, lout0, in_sizes[iperm]);

    const int nb0 = (n0 + WPB - 1) / WPB;
    const int nb1 = (n1 + WPB - 1) / WPB;
    const int nb2 = (n2 + WPB - 1) / WPB;

    dim3 grid(nb0 + nb1 + nb2, B);
    rocket_all_kernel<<<grid, WPB * 32>>>(
        x,
        w0, b0, off0, lout0, n0,
        w1, b1, off1, lout1, n1,
        w2, b2, off2, lout2, n2,
        (float*)d_out, nb0, nb1, stride);
}

// round 5
// speedup vs baseline: 2.3556x; 2.3556x over previous
#include <cuda_runtime.h>
#include <float.h>

#define L_SEQ 4096
#define N_TOTAL 512
#define WPB 8            // warps per block
#define PAD_MAX 4096     // P <= 4094
#define LP_MAX (L_SEQ + 2 * PAD_MAX)   // 12288 floats = 48KB static shared
#define MAX_B 64

__device__ int g_inv[N_TOTAL];
__device__ int g_P;
__device__ int g_ctr[MAX_B];

// Reset work counters, build inverse permutation, recover P.
__global__ void setup_kernel(const int* __restrict__ perm,
                             const int* __restrict__ off0,
                             const int* __restrict__ lout0,
                             int n_perm) {
    int j = threadIdx.x;
    if (j < MAX_B) g_ctr[j] = 0;
    if (j < n_perm) g_inv[perm[j]] = j;
    if (j == 0) {
        // ks=7 group: off0[6]-off0[0] = 6*d ; lout = L + 2*pad - 6*d
        int d6  = off0[6] - off0[0];
        int pad = (lout0[0] - L_SEQ + d6) / 2;
        g_P = off0[0] + pad;
    }
}

template<int KS>
__device__ __forceinline__ void run_group(
    const float* __restrict__ sx,          // zero-padded: x lives at [P, P+L)
    const float* __restrict__ w, const float* __restrict__ bias,
    const int*  __restrict__ off, const int* __restrict__ lout,
    float* __restrict__ out, int gi, int base, int b, int stride)
{
    const int lane = threadIdx.x & 31;

    float wk[KS];
    const float* pk[KS];
#pragma unroll
    for (int k = 0; k < KS; k++) {
        wk[k] = __ldg(&w[gi * KS + k]);
        pk[k] = sx + __ldg(&off[gi * KS + k]);   // index directly by t; never OOB
    }
    const float bsv = __ldg(&bias[gi]);
    const int   lo  = __ldg(&lout[gi]);

    float mx  = -FLT_MAX;
    int   cnt = 0;

    int t = lane;
    // unroll-by-2 main loop: two t per lane per iteration, no bounds checks
    for (; t + 32 < lo; t += 64) {
        float s0 = bsv, s1 = bsv;
#pragma unroll
        for (int k = 0; k < KS; k++) {
            s0 = fmaf(wk[k], pk[k][t],      s0);
            s1 = fmaf(wk[k], pk[k][t + 32], s1);
        }
        mx = fmaxf(mx, fmaxf(s0, s1));
        cnt += (s0 > 0.0f);
        cnt += (s1 > 0.0f);
    }
    for (; t < lo; t += 32) {
        float s = bsv;
#pragma unroll
        for (int k = 0; k < KS; k++)
            s = fmaf(wk[k], pk[k][t], s);
        mx = fmaxf(mx, s);
        cnt += (s > 0.0f);
    }

    // warp reductions
#pragma unroll
    for (int o = 16; o; o >>= 1) {
        mx   = fmaxf(mx, __shfl_xor_sync(0xffffffffu, mx, o));
        cnt += __shfl_xor_sync(0xffffffffu, cnt, o);
    }

    if (lane == 0) {
        int col = g_inv[base + gi];
        out[b * stride + 2 * col]     = mx;
        out[b * stride + 2 * col + 1] = (float)cnt / (float)lo;
    }
}

__global__ __launch_bounds__(WPB * 32)
void rocket_all_kernel(
    const float* __restrict__ x,
    const float* __restrict__ w0, const float* __restrict__ b0,
    const int*  __restrict__ off0, const int* __restrict__ lout0, int n0,
    const float* __restrict__ w1, const float* __restrict__ b1,
    const int*  __restrict__ off1, const int* __restrict__ lout1, int n1,
    const float* __restrict__ w2, const float* __restrict__ b2,
    const int*  __restrict__ off2, const int* __restrict__ lout2, int n2,
    float* __restrict__ out, int stride)
{
    __shared__ float sx[LP_MAX];
    const int b = blockIdx.y;
    const int P = g_P;
    const int N = n0 + n1 + n2;

    // zero only the pad regions [0,P) and [P+L, P+L+P)
    for (int i = threadIdx.x; i < P; i += WPB * 32) {
        sx[i]             = 0.0f;
        sx[P + L_SEQ + i] = 0.0f;
    }
    // stage x[b] into sx[P .. P+L): P is even (pads are 2*p0), float2-aligned
    {
        const float2* xb2 = (const float2*)(x + (size_t)b * L_SEQ);
        float2* dst = (float2*)(sx + P);
        for (int i = threadIdx.x; i < L_SEQ / 2; i += WPB * 32)
            dst[i] = xb2[i];
    }
    __syncthreads();

    const int lane = threadIdx.x & 31;

    // dynamic work-stealing: each warp pulls kernel indices for this batch
    for (;;) {
        int item = 0;
        if (lane == 0) item = atomicAdd(&g_ctr[b], 1);
        item = __shfl_sync(0xffffffffu, item, 0);
        if (item >= N) break;

        if (item < n0) {
            run_group<7>(sx, w0, b0, off0, lout0, out, item, 0, b, stride);
        } else if (item < n0 + n1) {
            run_group<9>(sx, w1, b1, off1, lout1, out, item - n0, n0, b, stride);
        } else {
            run_group<11>(sx, w2, b2, off2, lout2, out, item - n0 - n1, n0 + n1, b, stride);
        }
    }
}

extern "C" void kernel_launch(void* const* d_in, const int* in_sizes, int n_in,
                              void* d_out, int out_size) {
    // Two possible input orderings; disambiguate via sizes.
    // Dict order:      x, perm, P, w0,b0,off0,lout0, w1,b1,off1,lout1, w2,b2,off2,lout2
    // Signature order: x, w0,b0,off0,lout0, w1,b1,off1,lout1, w2,b2,off2,lout2, perm, P
    int ix, iperm, ig0, ig1, ig2;
    if (n_in >= 3 && in_sizes[1] == N_TOTAL && in_sizes[2] == 1) {
        ix = 0; iperm = 1; ig0 = 3; ig1 = 7; ig2 = 11;          // dict order
    } else {
        ix = 0; ig0 = 1; ig1 = 5; ig2 = 9; iperm = 13;          // signature order
    }

    const float* x     = (const float*)d_in[ix];
    const int*   perm  = (const int*)  d_in[iperm];

    const float* w0    = (const float*)d_in[ig0 + 0];
    const float* b0    = (const float*)d_in[ig0 + 1];
    const int*   off0  = (const int*)  d_in[ig0 + 2];
    const int*   lout0 = (const int*)  d_in[ig0 + 3];
    const float* w1    = (const float*)d_in[ig1 + 0];
    const float* b1    = (const float*)d_in[ig1 + 1];
    const int*   off1  = (const int*)  d_in[ig1 + 2];
    const int*   lout1 = (const int*)  d_in[ig1 + 3];
    const float* w2    = (const float*)d_in[ig2 + 0];
    const float* b2    = (const float*)d_in[ig2 + 1];
    const int*   off2  = (const int*)  d_in[ig2 + 2];
    const int*   lout2 = (const int*)  d_in[ig2 + 3];

    const int n0 = in_sizes[ig0 + 1];
    const int n1 = in_sizes[ig1 + 1];
    const int n2 = in_sizes[ig2 + 1];
    const int B  = in_sizes[ix] / L_SEQ;
    const int N  = n0 + n1 + n2;
    const int stride = 2 * N;

    setup_kernel<<<1, N_TOTAL>>>(perm, off0, lout0, in_sizes[iperm]);

    // persistent balanced grid: 4 blocks/SM * 148 SMs = 592 blocks total
    int bpb = 592 / (B > 0 ? B : 1);
    if (bpb < 1) bpb = 1;
    // don't launch more warps than work items per batch
    int max_bpb = (N + WPB - 1) / WPB;
    if (bpb > max_bpb) bpb = max_bpb;

    dim3 grid(bpb, B);
    rocket_all_kernel<<<grid, WPB * 32>>>(
        x,
        w0, b0, off0, lout0, n0,
        w1, b1, off1, lout1, n1,
        w2, b2, off2, lout2, n2,
        (float*)d_out, stride);
}

// round 6
// speedup vs baseline: 2.7206x; 1.1549x over previous
#include <cuda_runtime.h>
#include <float.h>

#define L_SEQ 4096
#define N_TOTAL 512
#define WPB 8            // warps per block
#define PAD_MAX 4096     // P <= 4094
#define LP_MAX (L_SEQ + 2 * PAD_MAX)   // 12288 floats = 48KB static shared
#define MAX_B 64

__device__ int g_inv[N_TOTAL];
__device__ int g_P;   // kept for reference/debug (padded array indexed by off directly)
__device__ int g_ctr[MAX_B];

// Reset work counters, build inverse permutation, recover P.
__global__ void setup_kernel(const int* __restrict__ perm,
                             const int* __restrict__ off0,
                             const int* __restrict__ lout0,
                             int n_perm) {
    int j = threadIdx.x;
    if (j < MAX_B) g_ctr[j] = 0;
    if (j < n_perm) g_inv[perm[j]] = j;
    if (j == 0) {
        int d6  = off0[6] - off0[0];
        int pad = (lout0[0] - L_SEQ + d6) / 2;
        g_P = off0[0] + pad;
    }
}

// Sliding-window 1D conv along m for one lane: outputs s_m = bsv + sum_k wk[k]*p[(m+k)*d],
// m in [0, steps). Window rotation fully unrolled (slots are compile-time const).
template<int KS>
__device__ __forceinline__ void conv_lane(
    const float* __restrict__ p, int steps, int d, float bsv,
    const float* __restrict__ wk, float& mx, int& cnt)
{
    if (steps <= 0) return;
    if (steps >= KS) {
        float y[KS];
#pragma unroll
        for (int j = 0; j < KS - 1; j++) y[j] = p[j * d];
        const float* pl = p + (KS - 1) * d;
        int i = 0;
        for (; i + KS <= steps; i += KS) {
#pragma unroll
            for (int u = 0; u < KS; u++) {
                y[(u + KS - 1) % KS] = *pl; pl += d;
                float s = bsv;
#pragma unroll
                for (int k = 0; k < KS; k++)
                    s = fmaf(wk[k], y[(u + k) % KS], s);
                mx = fmaxf(mx, s);
                cnt += (s > 0.0f);
            }
        }
        // tail (< KS outputs): direct taps
        for (; i < steps; i++) {
            const float* q = p + i * d;
            float s = bsv;
#pragma unroll
            for (int k = 0; k < KS; k++) s = fmaf(wk[k], q[k * d], s);
            mx = fmaxf(mx, s);
            cnt += (s > 0.0f);
        }
    } else {
        for (int i = 0; i < steps; i++) {
            const float* q = p + i * d;
            float s = bsv;
#pragma unroll
            for (int k = 0; k < KS; k++) s = fmaf(wk[k], q[k * d], s);
            mx = fmaxf(mx, s);
            cnt += (s > 0.0f);
        }
    }
}

template<int KS>
__device__ __forceinline__ void run_group(
    const float* __restrict__ sx,          // zero-padded: x lives at [P, P+L)
    const float* __restrict__ w, const float* __restrict__ bias,
    const int*  __restrict__ off, const int* __restrict__ lout,
    float* __restrict__ out, int gi, int base, int b, int stride)
{
    const int lane = threadIdx.x & 31;

    float wk[KS];
#pragma unroll
    for (int k = 0; k < KS; k++) wk[k] = __ldg(&w[gi * KS + k]);
    const int   o0  = __ldg(&off[gi * KS]);           // padded-array base for tap 0
    const int   d   = __ldg(&off[gi * KS + 1]) - o0;  // dilation
    const float bsv = __ldg(&bias[gi]);
    const int   lo  = __ldg(&lout[gi]);

    float mx  = -FLT_MAX;
    int   cnt = 0;
    const float* px = sx + o0;

    if (d < 32) {
        // lane -> (residue r, chunk g); uniform odd chunk size => conflict-free banks
        const int r = lane % d;
        const int g = lane / d;
        const int Mmax = (lo + d - 1) / d;
        const int Gmin = 32 / d;
        int mc = (Mmax + Gmin - 1) / Gmin;
        mc |= 1;                                   // round up to odd
        const int Mr = (r < lo) ? (lo - r + d - 1) / d : 0;
        int m0 = g * mc;
        int m1 = m0 + mc; if (m1 > Mr) m1 = Mr;
        if (m0 < m1)
            conv_lane<KS>(px + r + d * m0, m1 - m0, d, bsv, wk, mx, cnt);
    } else {
        // lanes = consecutive residues (consecutive addresses: conflict-free)
        for (int rb = 0; rb < d; rb += 32) {
            const int r = rb + lane;
            if (r < d) {
                const int Mr = (r < lo) ? (lo - r + d - 1) / d : 0;
                conv_lane<KS>(px + r, Mr, d, bsv, wk, mx, cnt);
            }
        }
    }

    // warp reductions
#pragma unroll
    for (int o = 16; o; o >>= 1) {
        mx   = fmaxf(mx, __shfl_xor_sync(0xffffffffu, mx, o));
        cnt += __shfl_xor_sync(0xffffffffu, cnt, o);
    }

    if (lane == 0) {
        int col = g_inv[base + gi];
        out[b * stride + 2 * col]     = mx;
        out[b * stride + 2 * col + 1] = (float)cnt / (float)lo;
    }
}

__global__ __launch_bounds__(WPB * 32)
void rocket_all_kernel(
    const float* __restrict__ x,
    const float* __restrict__ w0, const float* __restrict__ b0,
    const int*  __restrict__ off0, const int* __restrict__ lout0, int n0,
    const float* __restrict__ w1, const float* __restrict__ b1,
    const int*  __restrict__ off1, const int* __restrict__ lout1, int n1,
    const float* __restrict__ w2, const float* __restrict__ b2,
    const int*  __restrict__ off2, const int* __restrict__ lout2, int n2,
    float* __restrict__ out, int stride)
{
    __shared__ float sx[LP_MAX];
    const int b = blockIdx.y;
    const int P = g_P;
    const int N = n0 + n1 + n2;

    // zero pad regions [0,P) and [P+L, P+L+P)
    for (int i = threadIdx.x; i < P; i += WPB * 32) {
        sx[i]             = 0.0f;
        sx[P + L_SEQ + i] = 0.0f;
    }
    // stage x[b] into sx[P .. P+L): P even => float2-aligned
    {
        const float2* xb2 = (const float2*)(x + (size_t)b * L_SEQ);
        float2* dst = (float2*)(sx + P);
        for (int i = threadIdx.x; i < L_SEQ / 2; i += WPB * 32)
            dst[i] = xb2[i];
    }
    __syncthreads();

    const int lane = threadIdx.x & 31;

    // dynamic work-stealing: each warp pulls kernel indices for this batch
    for (;;) {
        int item = 0;
        if (lane == 0) item = atomicAdd(&g_ctr[b], 1);
        item = __shfl_sync(0xffffffffu, item, 0);
        if (item >= N) break;

        if (item < n0) {
            run_group<7>(sx, w0, b0, off0, lout0, out, item, 0, b, stride);
        } else if (item < n0 + n1) {
            run_group<9>(sx, w1, b1, off1, lout1, out, item - n0, n0, b, stride);
        } else {
            run_group<11>(sx, w2, b2, off2, lout2, out, item - n0 - n1, n0 + n1, b, stride);
        }
    }
}

extern "C" void kernel_launch(void* const* d_in, const int* in_sizes, int n_in,
                              void* d_out, int out_size) {
    // Dict order:      x, perm, P, w0,b0,off0,lout0, w1,b1,off1,lout1, w2,b2,off2,lout2
    // Signature order: x, w0,b0,off0,lout0, w1,b1,off1,lout1, w2,b2,off2,lout2, perm, P
    int ix, iperm, ig0, ig1, ig2;
    if (n_in >= 3 && in_sizes[1] == N_TOTAL && in_sizes[2] == 1) {
        ix = 0; iperm = 1; ig0 = 3; ig1 = 7; ig2 = 11;
    } else {
        ix = 0; ig0 = 1; ig1 = 5; ig2 = 9; iperm = 13;
    }

    const float* x     = (const float*)d_in[ix];
    const int*   perm  = (const int*)  d_in[iperm];

    const float* w0    = (const float*)d_in[ig0 + 0];
    const float* b0    = (const float*)d_in[ig0 + 1];
    const int*   off0  = (const int*)  d_in[ig0 + 2];
    const int*   lout0 = (const int*)  d_in[ig0 + 3];
    const float* w1    = (const float*)d_in[ig1 + 0];
    const float* b1    = (const float*)d_in[ig1 + 1];
    const int*   off1  = (const int*)  d_in[ig1 + 2];
    const int*   lout1 = (const int*)  d_in[ig1 + 3];
    const float* w2    = (const float*)d_in[ig2 + 0];
    const float* b2    = (const float*)d_in[ig2 + 1];
    const int*   off2  = (const int*)  d_in[ig2 + 2];
    const int*   lout2 = (const int*)  d_in[ig2 + 3];

    const int n0 = in_sizes[ig0 + 1];
    const int n1 = in_sizes[ig1 + 1];
    const int n2 = in_sizes[ig2 + 1];
    const int B  = in_sizes[ix] / L_SEQ;
    const int N  = n0 + n1 + n2;
    const int stride = 2 * N;

    setup_kernel<<<1, N_TOTAL>>>(perm, off0, lout0, in_sizes[iperm]);

    // persistent balanced grid: ~4 blocks/SM * 148 SMs
    int bpb = 592 / (B > 0 ? B : 1);
    if (bpb < 1) bpb = 1;
    int max_bpb = (N + WPB - 1) / WPB;
    if (bpb > max_bpb) bpb = max_bpb;

    dim3 grid(bpb, B);
    rocket_all_kernel<<<grid, WPB * 32>>>(
        x,
        w0, b0, off0, lout0, n0,
        w1, b1, off1, lout1, n1,
        w2, b2, off2, lout2, n2,
        (float*)d_out, stride);
}